// round 15
// baseline (speedup 1.0000x reference)
#include <cuda_runtime.h>
#include <cstdint>
#include <cstddef>

// ---------------------------------------------------------------------------
// MultiHeadAttention fused block (round 14: BM=256 GEMM tiles, 512 threads,
// 16 warps -- cuts cp.async staging traffic 25% and halves CTA count).
// Flash + LN unchanged from round 13.
// ---------------------------------------------------------------------------

#define B_SZ   4
#define S_SZ   2048
#define D_SZ   1024
#define H_SZ   16
#define DH_SZ  64
#define M_SZ   (B_SZ * S_SZ)          // 8192

#define PK 68   // K/V pitch (words): 68 % 32 == 4 -> conflict-free everywhere
#define STAGE_W (128 * PK)            // 64 K rows + 64 V rows per stage
#define FLASH_SMEM_B (3 * STAGE_W * 4)      // 104448 B

#define GP 36                          // gemm smem pitch (36 % 32 == 4)
#define GBM 256                        // gemm tile rows
#define GBN 128                        // gemm tile cols
#define GSTAGE ((GBM + GBN) * GP)      // words per stage = 13824
#define GEMM_SMEM_B (3 * GSTAGE * 4)   // 165888 B (<= 227 KB cap)

__device__ float g_q[M_SZ * D_SZ];
__device__ float g_k[M_SZ * D_SZ];
__device__ float g_v[M_SZ * D_SZ];
__device__ float g_ctx[M_SZ * D_SZ];

__device__ __forceinline__ uint32_t f2tf32(float x) {
    uint32_t r;
    asm("cvt.rna.tf32.f32 %0, %1;" : "=r"(r) : "f"(x));
    return r;
}

__device__ __forceinline__ void mma16n8k8(float c[4], const uint32_t a[4],
                                          const uint32_t b[2]) {
    asm volatile(
        "mma.sync.aligned.m16n8k8.row.col.f32.tf32.tf32.f32 "
        "{%0,%1,%2,%3}, {%4,%5,%6,%7}, {%8,%9}, {%0,%1,%2,%3};\n"
        : "+f"(c[0]), "+f"(c[1]), "+f"(c[2]), "+f"(c[3])
        : "r"(a[0]), "r"(a[1]), "r"(a[2]), "r"(a[3]), "r"(b[0]), "r"(b[1]));
}

__device__ __forceinline__ void cp16(uint32_t smem_dst, const void* gmem_src) {
    asm volatile("cp.async.cg.shared.global [%0], [%1], 16;\n"
                 :: "r"(smem_dst), "l"(gmem_src));
}

__device__ __forceinline__ void ldsm_x4(uint32_t d[4], uint32_t addr) {
    asm volatile("ldmatrix.sync.aligned.m8n8.x4.shared.b16 {%0,%1,%2,%3}, [%4];"
                 : "=r"(d[0]), "=r"(d[1]), "=r"(d[2]), "=r"(d[3]) : "r"(addr));
}

// ---------------------------------------------------------------------------
// Pipelined tf32 GEMM mainloop: 256x128 tile, 512 threads (16 warps, 4x4
// warp grid, 64x32 warp tile), 3-stage cp.async, ldmatrix fragment loads.
// ---------------------------------------------------------------------------
__device__ __forceinline__ void gemm_mainloop(
    const float* __restrict__ A, const float* __restrict__ W,
    int m0, int n0, uint32_t sbase, float acc[4][4][4])
{
    const int tid  = threadIdx.x;
    const int lane = tid & 31;
    const int warp = tid >> 5;
    const int wm   = (warp & 3) * 64;
    const int wn   = (warp >> 2) * 32;
    const int lm8  = lane & 7;
    const int m4   = lane >> 3;
    const int lr   = tid >> 3;          // 0..63
    const int lc   = (tid & 7) << 2;    // 0,4,...,28

#pragma unroll
    for (int mi = 0; mi < 4; mi++)
#pragma unroll
        for (int ni = 0; ni < 4; ni++)
#pragma unroll
            for (int c = 0; c < 4; c++) acc[mi][ni][c] = 0.f;

    auto issue = [&](int k0, int stage) {
        const uint32_t ab = sbase + (stage * GSTAGE) * 4;
        const uint32_t bb = ab + (GBM * GP) * 4;
#pragma unroll
        for (int u = 0; u < 4; u++) {   // A: 256 rows
            const int row = lr + 64 * u;
            cp16(ab + (row * GP + lc) * 4, A + (size_t)(m0 + row) * D_SZ + k0 + lc);
        }
#pragma unroll
        for (int u = 0; u < 2; u++) {   // B: 128 rows
            const int row = lr + 64 * u;
            cp16(bb + (row * GP + lc) * 4, W + (size_t)(n0 + row) * D_SZ + k0 + lc);
        }
        asm volatile("cp.async.commit_group;\n");
    };

    issue(0, 0);
    issue(32, 1);

    const int a_row = (m4 & 1) * 8 + lm8;
    const int a_col = (m4 >> 1) * 4;
    const int b_row = (m4 >> 1) * 8 + lm8;
    const int b_col = (m4 & 1) * 4;

    const int NK = D_SZ / 32;   // 32
    int s = 0;                  // stage of tile kt (cycles 0,1,2)
    for (int kt = 0; kt < NK; kt++) {
        if (kt + 1 < NK) asm volatile("cp.async.wait_group 1;\n");
        else             asm volatile("cp.async.wait_group 0;\n");
        __syncthreads();

        if (kt + 2 < NK) {
            int s2 = s + 2; if (s2 >= 3) s2 -= 3;   // consumed last iter
            issue((kt + 2) * 32, s2);
        }

        const uint32_t aw = sbase + (s * GSTAGE) * 4;
        const uint32_t bw = aw + (GBM * GP) * 4;

#pragma unroll
        for (int kk = 0; kk < 32; kk += 8) {
            uint32_t af[4][4], bf[4][2];
#pragma unroll
            for (int mi = 0; mi < 4; mi++)
                ldsm_x4(af[mi],
                        aw + ((wm + mi * 16 + a_row) * GP + kk + a_col) * 4);
#pragma unroll
            for (int np = 0; np < 4; np += 2)
                ldsm_x4(&bf[np][0],
                        bw + ((wn + np * 8 + b_row) * GP + kk + b_col) * 4);
#pragma unroll
            for (int mi = 0; mi < 4; mi++)
#pragma unroll
                for (int ni = 0; ni < 4; ni++)
                    mma16n8k8(acc[mi][ni], af[mi], bf[ni]);
        }

        if (++s == 3) s = 0;
    }
}

// ---------------------------------------------------------------------------
// Fused Q/K/V projection GEMM.
// ---------------------------------------------------------------------------
__global__ void __launch_bounds__(512, 1)
gemm_qkv(const float* __restrict__ Qin, const float* __restrict__ Kin,
         const float* __restrict__ Vin,
         const float* __restrict__ Wq, const float* __restrict__ Wk,
         const float* __restrict__ Wv,
         const float* __restrict__ bq, const float* __restrict__ bk,
         const float* __restrict__ bv)
{
    extern __shared__ uint32_t smbuf[];
    const uint32_t sbase = (uint32_t)__cvta_generic_to_shared(smbuf);

    const int mode = blockIdx.z;
    const float* A    = (mode == 0) ? Qin : (mode == 1) ? Kin : Vin;
    const float* W    = (mode == 0) ? Wq  : (mode == 1) ? Wk  : Wv;
    const float* bias = (mode == 0) ? bq  : (mode == 1) ? bk  : bv;
    float* out        = (mode == 0) ? g_q : (mode == 1) ? g_k : g_v;

    const int m0 = blockIdx.y * GBM;
    const int n0 = blockIdx.x * GBN;

    float acc[4][4][4];
    gemm_mainloop(A, W, m0, n0, sbase, acc);

    const int lane = threadIdx.x & 31;
    const int warp = threadIdx.x >> 5;
    const int wm = (warp & 3) * 64, wn = (warp >> 2) * 32;
    const int g = lane >> 2, tg = lane & 3;

#pragma unroll
    for (int mi = 0; mi < 4; mi++)
#pragma unroll
        for (int ni = 0; ni < 4; ni++)
#pragma unroll
            for (int h = 0; h < 2; h++) {
                const int m = m0 + wm + mi * 16 + g + h * 8;
                const int n = n0 + wn + ni * 8 + tg * 2;
                const int bI = m >> 11, s = m & 2047;
                const int head = n >> 6, dd = n & 63;
                float2 val;
                val.x = acc[mi][ni][h * 2 + 0] + bias[n];
                val.y = acc[mi][ni][h * 2 + 1] + bias[n + 1];
                *(float2*)&out[((size_t)(bI * H_SZ + head) << 17)
                               + ((size_t)s << 6) + dd] = val;
            }
}

// ---------------------------------------------------------------------------
// Output projection GEMM: x = g_ctx @ Wo^T + bo + resid -> g_q.
// ---------------------------------------------------------------------------
__global__ void __launch_bounds__(512, 1)
gemm_o(const float* __restrict__ Wo, const float* __restrict__ bo,
       const float* __restrict__ resid)
{
    extern __shared__ uint32_t smbuf[];
    const uint32_t sbase = (uint32_t)__cvta_generic_to_shared(smbuf);

    const int m0 = blockIdx.y * GBM;
    const int n0 = blockIdx.x * GBN;

    float acc[4][4][4];
    gemm_mainloop((const float*)g_ctx, Wo, m0, n0, sbase, acc);

    const int lane = threadIdx.x & 31;
    const int warp = threadIdx.x >> 5;
    const int wm = (warp & 3) * 64, wn = (warp >> 2) * 32;
    const int g = lane >> 2, tg = lane & 3;

#pragma unroll
    for (int mi = 0; mi < 4; mi++)
#pragma unroll
        for (int ni = 0; ni < 4; ni++)
#pragma unroll
            for (int h = 0; h < 2; h++) {
                const int m = m0 + wm + mi * 16 + g + h * 8;
                const int n = n0 + wn + ni * 8 + tg * 2;
                const size_t idx = (size_t)m * D_SZ + n;
                const float2 r2 = *(const float2*)&resid[idx];
                float2 val;
                val.x = acc[mi][ni][h * 2 + 0] + bo[n]     + r2.x;
                val.y = acc[mi][ni][h * 2 + 1] + bo[n + 1] + r2.y;
                *(float2*)&g_q[idx] = val;
            }
}

// ---------------------------------------------------------------------------
// Flash attention: tf32 mma, 3-stage cp.async KV pipeline, ldmatrix K-frags,
// zero-shuffle permuted-contraction PV (unchanged from round 13).
// ---------------------------------------------------------------------------
__global__ void __launch_bounds__(256, 2)
flash_mma(const int* __restrict__ mask)
{
    extern __shared__ uint32_t smbuf[];

    const int b    = blockIdx.z;
    const int h    = blockIdx.y;
    const int q0   = blockIdx.x * 128;
    const int tid  = threadIdx.x;
    const int lane = tid & 31;
    const int warp = tid >> 5;
    const int g    = lane >> 2;
    const int tg   = lane & 3;
    const int lm8  = lane & 7;
    const int m4   = lane >> 3;

    const size_t bh = (size_t)(b * H_SZ + h) * (S_SZ * DH_SZ);
    const uint32_t sbase = (uint32_t)__cvta_generic_to_shared(smbuf);

    // Stage 128 Q rows (raw bits) into stage 0, extract frags, then recycle.
    {
        const float4* gq = (const float4*)(g_q + bh + (size_t)q0 * DH_SZ);
        for (int idx = tid; idx < 2048; idx += 256) {
            const int r = idx >> 4, c = (idx & 15) << 2;
            cp16(sbase + (r * PK + c) * 4, gq + idx);
        }
        asm volatile("cp.async.commit_group;\n");
        asm volatile("cp.async.wait_group 0;\n");
        __syncthreads();
    }

    uint32_t qf[8][4];
    {
        const int r = warp * 16 + g;
        const uint32_t* b0 = &smbuf[r * PK];
        const uint32_t* b1 = &smbuf[(r + 8) * PK];
#pragma unroll
        for (int k8 = 0; k8 < 8; k8++) {
            const int k = k8 * 8;
            qf[k8][0] = f2tf32(0.125f * __uint_as_float(b0[k + tg]));
            qf[k8][1] = f2tf32(0.125f * __uint_as_float(b1[k + tg]));
            qf[k8][2] = f2tf32(0.125f * __uint_as_float(b0[k + tg + 4]));
            qf[k8][3] = f2tf32(0.125f * __uint_as_float(b1[k + tg + 4]));
        }
    }
    __syncthreads();

    const float4* gkb = (const float4*)(g_k + bh);
    const float4* gvb = (const float4*)(g_v + bh);

    auto issue_tile = [&](int t, int stage) {
        const uint32_t kb = sbase + (stage * STAGE_W) * 4;
        const uint32_t vb = kb + (64 * PK) * 4;
        const float4* gk = gkb + (size_t)t * 1024;
        const float4* gv = gvb + (size_t)t * 1024;
#pragma unroll
        for (int u = 0; u < 4; u++) {
            const int idx = tid + 256 * u;
            const int r = idx >> 4, c = (idx & 15) << 2;
            cp16(kb + (r * PK + c) * 4, gk + idx);
            cp16(vb + (r * PK + c) * 4, gv + idx);
        }
        asm volatile("cp.async.commit_group;\n");
    };

    issue_tile(0, 0);
    issue_tile(1, 1);

    float of[8][4];
#pragma unroll
    for (int ni = 0; ni < 8; ni++)
#pragma unroll
        for (int c = 0; c < 4; c++) of[ni][c] = 0.f;
    float m0 = -1e30f, m1 = -1e30f, l0 = 0.f, l1 = 0.f;

    const int* mrow = mask + b * S_SZ;
    const int NT = S_SZ / 64;   // 32

    const int kq_col = (m4 >> 1) * 8 + (m4 & 1) * 4;

    int s = 0;   // stage of tile t (cycles 0,1,2)
    for (int t = 0; t < NT; t++) {
        if (t + 1 < NT) asm volatile("cp.async.wait_group 1;\n");
        else            asm volatile("cp.async.wait_group 0;\n");
        __syncthreads();

        if (t + 2 < NT) {
            int s2 = s + 2; if (s2 >= 3) s2 -= 3;   // consumed last iter
            issue_tile(t + 2, s2);
        }

        const uint32_t kwb = sbase + (s * STAGE_W) * 4;
        const uint32_t* VsS = &smbuf[s * STAGE_W + 64 * PK];

        // S = (Q/8) K^T
        float s_[8][4];
#pragma unroll
        for (int nt = 0; nt < 8; nt++) {
            s_[nt][0] = 0.f; s_[nt][1] = 0.f; s_[nt][2] = 0.f; s_[nt][3] = 0.f;
#pragma unroll
            for (int k8g = 0; k8g < 4; k8g++) {
                uint32_t d[4];
                ldsm_x4(d, kwb + ((nt * 8 + lm8) * PK + k8g * 16 + kq_col) * 4);
                mma16n8k8(s_[nt], qf[2 * k8g],     &d[0]);
                mma16n8k8(s_[nt], qf[2 * k8g + 1], &d[2]);
            }
        }

        // mask (additive), int2 loads
#pragma unroll
        for (int nt = 0; nt < 8; nt++) {
            const int2 mm = *(const int2*)&mrow[t * 64 + nt * 8 + tg * 2];
            const float ma = (mm.x == 0) ? -1e9f : 0.f;
            const float mb = (mm.y == 0) ? -1e9f : 0.f;
            s_[nt][0] += ma; s_[nt][1] += mb;
            s_[nt][2] += ma; s_[nt][3] += mb;
        }

        // online softmax: rows g (c0,c1) and g+8 (c2,c3), quad-lane reduce
        float rm0 = -1e30f, rm1 = -1e30f;
#pragma unroll
        for (int nt = 0; nt < 8; nt++) {
            rm0 = fmaxf(rm0, fmaxf(s_[nt][0], s_[nt][1]));
            rm1 = fmaxf(rm1, fmaxf(s_[nt][2], s_[nt][3]));
        }
        rm0 = fmaxf(rm0, __shfl_xor_sync(0xffffffffu, rm0, 1));
        rm0 = fmaxf(rm0, __shfl_xor_sync(0xffffffffu, rm0, 2));
        rm1 = fmaxf(rm1, __shfl_xor_sync(0xffffffffu, rm1, 1));
        rm1 = fmaxf(rm1, __shfl_xor_sync(0xffffffffu, rm1, 2));

        const float mn0 = fmaxf(m0, rm0);
        const float mn1 = fmaxf(m1, rm1);
        const float al0 = __expf(m0 - mn0);
        const float al1 = __expf(m1 - mn1);
        m0 = mn0; m1 = mn1;

        float rs0 = 0.f, rs1 = 0.f;
#pragma unroll
        for (int nt = 0; nt < 8; nt++) {
            s_[nt][0] = __expf(s_[nt][0] - mn0);
            s_[nt][1] = __expf(s_[nt][1] - mn0);
            s_[nt][2] = __expf(s_[nt][2] - mn1);
            s_[nt][3] = __expf(s_[nt][3] - mn1);
            rs0 += s_[nt][0] + s_[nt][1];
            rs1 += s_[nt][2] + s_[nt][3];
        }
        rs0 += __shfl_xor_sync(0xffffffffu, rs0, 1);
        rs0 += __shfl_xor_sync(0xffffffffu, rs0, 2);
        rs1 += __shfl_xor_sync(0xffffffffu, rs1, 1);
        rs1 += __shfl_xor_sync(0xffffffffu, rs1, 2);
        l0 = l0 * al0 + rs0;
        l1 = l1 * al1 + rs1;

#pragma unroll
        for (int ni = 0; ni < 8; ni++) {
            of[ni][0] *= al0; of[ni][1] *= al0;
            of[ni][2] *= al1; of[ni][3] *= al1;
        }

        // O += P V : permuted contraction, C-frag reused directly as A-frag
#pragma unroll
        for (int j = 0; j < 8; j++) {
            uint32_t pa[4];
            pa[0] = __float_as_uint(s_[j][0]);
            pa[1] = __float_as_uint(s_[j][2]);
            pa[2] = __float_as_uint(s_[j][1]);
            pa[3] = __float_as_uint(s_[j][3]);
            const uint32_t* vr0 = &VsS[(j * 8 + 2 * tg)     * PK];
            const uint32_t* vr1 = &VsS[(j * 8 + 2 * tg + 1) * PK];
#pragma unroll
            for (int ni = 0; ni < 8; ni++) {
                uint32_t bf[2];
                bf[0] = vr0[ni * 8 + g];
                bf[1] = vr1[ni * 8 + g];
                mma16n8k8(of[ni], pa, bf);
            }
        }

        if (++s == 3) s = 0;
    }

    const float il0 = 1.f / l0;
    const float il1 = 1.f / l1;
    const int row0 = b * S_SZ + q0 + warp * 16 + g;
    const int colb = h * DH_SZ;
#pragma unroll
    for (int ni = 0; ni < 8; ni++) {
        const int col = colb + ni * 8 + tg * 2;
        float2 v0, v1;
        v0.x = of[ni][0] * il0; v0.y = of[ni][1] * il0;
        v1.x = of[ni][2] * il1; v1.y = of[ni][3] * il1;
        *(float2*)&g_ctx[(size_t)row0 * D_SZ + col]       = v0;
        *(float2*)&g_ctx[(size_t)(row0 + 8) * D_SZ + col] = v1;
    }
}

// ---------------------------------------------------------------------------
// LayerNorm over last dim (1024). float4 vectorized, two-pass (exact).
// ---------------------------------------------------------------------------
__global__ void __launch_bounds__(256)
ln_kernel(const float* __restrict__ gamma, const float* __restrict__ beta,
          float* __restrict__ out)
{
    __shared__ float red[8];
    const int row = blockIdx.x;
    const int tid = threadIdx.x;
    const float4 v = ((const float4*)(g_q + (size_t)row * D_SZ))[tid];

    float s = v.x + v.y + v.z + v.w;
#pragma unroll
    for (int off = 16; off > 0; off >>= 1)
        s += __shfl_xor_sync(0xffffffffu, s, off);
    if ((tid & 31) == 0) red[tid >> 5] = s;
    __syncthreads();
    float tot = 0.f;
#pragma unroll
    for (int w = 0; w < 8; w++) tot += red[w];
    const float mu = tot * (1.f / 1024.f);

    const float d0 = v.x - mu, d1 = v.y - mu, d2 = v.z - mu, d3 = v.w - mu;
    float ss = d0 * d0 + d1 * d1 + d2 * d2 + d3 * d3;
#pragma unroll
    for (int off = 16; off > 0; off >>= 1)
        ss += __shfl_xor_sync(0xffffffffu, ss, off);
    __syncthreads();
    if ((tid & 31) == 0) red[tid >> 5] = ss;
    __syncthreads();
    float vtot = 0.f;
#pragma unroll
    for (int w = 0; w < 8; w++) vtot += red[w];
    const float inv = rsqrtf(vtot * (1.f / 1024.f) + 1e-5f);

    const float4 ga = ((const float4*)gamma)[tid];
    const float4 be = ((const float4*)beta)[tid];
    float4 o;
    o.x = ga.x * d0 * inv + be.x;
    o.y = ga.y * d1 * inv + be.y;
    o.z = ga.z * d2 * inv + be.z;
    o.w = ga.w * d3 * inv + be.w;
    ((float4*)(out + (size_t)row * D_SZ))[tid] = o;
}

// ---------------------------------------------------------------------------
extern "C" void kernel_launch(void* const* d_in, const int* in_sizes, int n_in,
                              void* d_out, int out_size)
{
    const float* Q     = (const float*)d_in[0];
    const float* K     = (const float*)d_in[1];
    const float* V     = (const float*)d_in[2];
    const int*   mask  = (const int*)  d_in[3];
    const float* Wq    = (const float*)d_in[4];
    const float* bq    = (const float*)d_in[5];
    const float* Wk    = (const float*)d_in[6];
    const float* bk    = (const float*)d_in[7];
    const float* Wv    = (const float*)d_in[8];
    const float* bv    = (const float*)d_in[9];
    const float* Wo    = (const float*)d_in[10];
    const float* bo    = (const float*)d_in[11];
    const float* gamma = (const float*)d_in[12];
    const float* beta  = (const float*)d_in[13];
    float* out = (float*)d_out;

    cudaFuncSetAttribute(flash_mma,
                         cudaFuncAttributeMaxDynamicSharedMemorySize,
                         FLASH_SMEM_B);
    cudaFuncSetAttribute(gemm_qkv,
                         cudaFuncAttributeMaxDynamicSharedMemorySize,
                         GEMM_SMEM_B);
    cudaFuncSetAttribute(gemm_o,
                         cudaFuncAttributeMaxDynamicSharedMemorySize,
                         GEMM_SMEM_B);
    (void)cudaGetLastError();

    const dim3 qkv_grid(D_SZ / GBN, M_SZ / GBM, 3);   // (8, 32, 3)
    const dim3 o_grid(D_SZ / GBN, M_SZ / GBM);        // (8, 32)

    gemm_qkv<<<qkv_grid, 512, GEMM_SMEM_B>>>(Q, K, V, Wq, Wk, Wv, bq, bk, bv);

    flash_mma<<<dim3(S_SZ / 128, H_SZ, B_SZ), 256, FLASH_SMEM_B>>>(mask);

    gemm_o<<<o_grid, 512, GEMM_SMEM_B>>>(Wo, bo, Q);

    ln_kernel<<<M_SZ, 256>>>(gamma, beta, out);
}

// round 16
// speedup vs baseline: 1.0500x; 1.0500x over previous
#include <cuda_runtime.h>
#include <cstdint>
#include <cstddef>

// ---------------------------------------------------------------------------
// MultiHeadAttention fused block (round 15: revert GEMMs to round-13 config
// [BM=256 regressed]; flash softmax in exp2 domain + warp-vote rescale skip).
// ---------------------------------------------------------------------------

#define B_SZ   4
#define S_SZ   2048
#define D_SZ   1024
#define H_SZ   16
#define DH_SZ  64
#define M_SZ   (B_SZ * S_SZ)          // 8192

#define PK 68   // K/V pitch (words): 68 % 32 == 4 -> conflict-free everywhere
#define STAGE_W (128 * PK)            // 64 K rows + 64 V rows per stage
#define FLASH_SMEM_B (3 * STAGE_W * 4)      // 104448 B

#define GP 36                          // gemm smem pitch (36 % 32 == 4)
#define GSTAGE (128 * GP * 2)
#define GEMM_SMEM_B (3 * GSTAGE * 4)   // 110592 B

#define LOG2E 1.44269504088896340736f

__device__ float g_q[M_SZ * D_SZ];
__device__ float g_k[M_SZ * D_SZ];
__device__ float g_v[M_SZ * D_SZ];
__device__ float g_ctx[M_SZ * D_SZ];

__device__ __forceinline__ uint32_t f2tf32(float x) {
    uint32_t r;
    asm("cvt.rna.tf32.f32 %0, %1;" : "=r"(r) : "f"(x));
    return r;
}

__device__ __forceinline__ void mma16n8k8(float c[4], const uint32_t a[4],
                                          const uint32_t b[2]) {
    asm volatile(
        "mma.sync.aligned.m16n8k8.row.col.f32.tf32.tf32.f32 "
        "{%0,%1,%2,%3}, {%4,%5,%6,%7}, {%8,%9}, {%0,%1,%2,%3};\n"
        : "+f"(c[0]), "+f"(c[1]), "+f"(c[2]), "+f"(c[3])
        : "r"(a[0]), "r"(a[1]), "r"(a[2]), "r"(a[3]), "r"(b[0]), "r"(b[1]));
}

__device__ __forceinline__ void cp16(uint32_t smem_dst, const void* gmem_src) {
    asm volatile("cp.async.cg.shared.global [%0], [%1], 16;\n"
                 :: "r"(smem_dst), "l"(gmem_src));
}

__device__ __forceinline__ void ldsm_x4(uint32_t d[4], uint32_t addr) {
    asm volatile("ldmatrix.sync.aligned.m8n8.x4.shared.b16 {%0,%1,%2,%3}, [%4];"
                 : "=r"(d[0]), "=r"(d[1]), "=r"(d[2]), "=r"(d[3]) : "r"(addr));
}

// ---------------------------------------------------------------------------
// Pipelined tf32 GEMM mainloop (round 13, proven best): 128x128 tile, 256
// threads, 3-stage cp.async, ldmatrix fragment loads, one barrier per k-tile.
// ---------------------------------------------------------------------------
__device__ __forceinline__ void gemm_mainloop(
    const float* __restrict__ A, const float* __restrict__ W,
    int m0, int n0, uint32_t sbase, float acc[4][4][4])
{
    const int tid  = threadIdx.x;
    const int lane = tid & 31;
    const int warp = tid >> 5;
    const int wm   = (warp & 1) * 64;
    const int wn   = (warp >> 1) * 32;
    const int lm8  = lane & 7;
    const int m4   = lane >> 3;
    const int lr   = tid >> 3;
    const int lc   = (tid & 7) << 2;

#pragma unroll
    for (int mi = 0; mi < 4; mi++)
#pragma unroll
        for (int ni = 0; ni < 4; ni++)
#pragma unroll
            for (int c = 0; c < 4; c++) acc[mi][ni][c] = 0.f;

    auto issue = [&](int k0, int stage) {
        const uint32_t ab = sbase + (stage * GSTAGE) * 4;
        const uint32_t bb = ab + (128 * GP) * 4;
#pragma unroll
        for (int u = 0; u < 4; u++) {
            const int row = lr + 32 * u;
            cp16(ab + (row * GP + lc) * 4, A + (size_t)(m0 + row) * D_SZ + k0 + lc);
            cp16(bb + (row * GP + lc) * 4, W + (size_t)(n0 + row) * D_SZ + k0 + lc);
        }
        asm volatile("cp.async.commit_group;\n");
    };

    issue(0, 0);
    issue(32, 1);

    const int a_row = (m4 & 1) * 8 + lm8;
    const int a_col = (m4 >> 1) * 4;
    const int b_row = (m4 >> 1) * 8 + lm8;
    const int b_col = (m4 & 1) * 4;

    const int NK = D_SZ / 32;   // 32
    int s = 0;
    for (int kt = 0; kt < NK; kt++) {
        if (kt + 1 < NK) asm volatile("cp.async.wait_group 1;\n");
        else             asm volatile("cp.async.wait_group 0;\n");
        __syncthreads();

        if (kt + 2 < NK) {
            int s2 = s + 2; if (s2 >= 3) s2 -= 3;   // consumed last iter
            issue((kt + 2) * 32, s2);
        }

        const uint32_t aw = sbase + (s * GSTAGE) * 4;
        const uint32_t bw = aw + (128 * GP) * 4;

#pragma unroll
        for (int kk = 0; kk < 32; kk += 8) {
            uint32_t af[4][4], bf[4][2];
#pragma unroll
            for (int mi = 0; mi < 4; mi++)
                ldsm_x4(af[mi],
                        aw + ((wm + mi * 16 + a_row) * GP + kk + a_col) * 4);
#pragma unroll
            for (int np = 0; np < 4; np += 2)
                ldsm_x4(&bf[np][0],
                        bw + ((wn + np * 8 + b_row) * GP + kk + b_col) * 4);
#pragma unroll
            for (int mi = 0; mi < 4; mi++)
#pragma unroll
                for (int ni = 0; ni < 4; ni++)
                    mma16n8k8(acc[mi][ni], af[mi], bf[ni]);
        }

        if (++s == 3) s = 0;
    }
}

// ---------------------------------------------------------------------------
// Fused Q/K/V projection GEMM.
// ---------------------------------------------------------------------------
__global__ void __launch_bounds__(256, 2)
gemm_qkv(const float* __restrict__ Qin, const float* __restrict__ Kin,
         const float* __restrict__ Vin,
         const float* __restrict__ Wq, const float* __restrict__ Wk,
         const float* __restrict__ Wv,
         const float* __restrict__ bq, const float* __restrict__ bk,
         const float* __restrict__ bv)
{
    extern __shared__ uint32_t smbuf[];
    const uint32_t sbase = (uint32_t)__cvta_generic_to_shared(smbuf);

    const int mode = blockIdx.z;
    const float* A    = (mode == 0) ? Qin : (mode == 1) ? Kin : Vin;
    const float* W    = (mode == 0) ? Wq  : (mode == 1) ? Wk  : Wv;
    const float* bias = (mode == 0) ? bq  : (mode == 1) ? bk  : bv;
    float* out        = (mode == 0) ? g_q : (mode == 1) ? g_k : g_v;

    const int m0 = blockIdx.y * 128;
    const int n0 = blockIdx.x * 128;

    float acc[4][4][4];
    gemm_mainloop(A, W, m0, n0, sbase, acc);

    const int lane = threadIdx.x & 31;
    const int warp = threadIdx.x >> 5;
    const int wm = (warp & 1) * 64, wn = (warp >> 1) * 32;
    const int g = lane >> 2, tg = lane & 3;

#pragma unroll
    for (int mi = 0; mi < 4; mi++)
#pragma unroll
        for (int ni = 0; ni < 4; ni++)
#pragma unroll
            for (int h = 0; h < 2; h++) {
                const int m = m0 + wm + mi * 16 + g + h * 8;
                const int n = n0 + wn + ni * 8 + tg * 2;
                const int bI = m >> 11, s = m & 2047;
                const int head = n >> 6, dd = n & 63;
                float2 val;
                val.x = acc[mi][ni][h * 2 + 0] + bias[n];
                val.y = acc[mi][ni][h * 2 + 1] + bias[n + 1];
                *(float2*)&out[((size_t)(bI * H_SZ + head) << 17)
                               + ((size_t)s << 6) + dd] = val;
            }
}

// ---------------------------------------------------------------------------
// Output projection GEMM: x = g_ctx @ Wo^T + bo + resid -> g_q.
// ---------------------------------------------------------------------------
__global__ void __launch_bounds__(256, 2)
gemm_o(const float* __restrict__ Wo, const float* __restrict__ bo,
       const float* __restrict__ resid)
{
    extern __shared__ uint32_t smbuf[];
    const uint32_t sbase = (uint32_t)__cvta_generic_to_shared(smbuf);

    const int m0 = blockIdx.y * 128;
    const int n0 = blockIdx.x * 128;

    float acc[4][4][4];
    gemm_mainloop((const float*)g_ctx, Wo, m0, n0, sbase, acc);

    const int lane = threadIdx.x & 31;
    const int warp = threadIdx.x >> 5;
    const int wm = (warp & 1) * 64, wn = (warp >> 1) * 32;
    const int g = lane >> 2, tg = lane & 3;

#pragma unroll
    for (int mi = 0; mi < 4; mi++)
#pragma unroll
        for (int ni = 0; ni < 4; ni++)
#pragma unroll
            for (int h = 0; h < 2; h++) {
                const int m = m0 + wm + mi * 16 + g + h * 8;
                const int n = n0 + wn + ni * 8 + tg * 2;
                const size_t idx = (size_t)m * D_SZ + n;
                const float2 r2 = *(const float2*)&resid[idx];
                float2 val;
                val.x = acc[mi][ni][h * 2 + 0] + bo[n]     + r2.x;
                val.y = acc[mi][ni][h * 2 + 1] + bo[n + 1] + r2.y;
                *(float2*)&g_q[idx] = val;
            }
}

// ---------------------------------------------------------------------------
// Flash attention: tf32 mma, 3-stage cp.async KV pipeline, ldmatrix K-frags,
// zero-shuffle permuted-contraction PV. Softmax runs in the exp2 domain
// (log2e folded into the Q pre-scale and mask constant); the O-rescale loop
// is skipped by warp vote when no row's max increased (exp2f(0)==1 exactly).
// ---------------------------------------------------------------------------
__global__ void __launch_bounds__(256, 2)
flash_mma(const int* __restrict__ mask)
{
    extern __shared__ uint32_t smbuf[];

    const int b    = blockIdx.z;
    const int h    = blockIdx.y;
    const int q0   = blockIdx.x * 128;
    const int tid  = threadIdx.x;
    const int lane = tid & 31;
    const int warp = tid >> 5;
    const int g    = lane >> 2;
    const int tg   = lane & 3;
    const int lm8  = lane & 7;
    const int m4   = lane >> 3;

    const size_t bh = (size_t)(b * H_SZ + h) * (S_SZ * DH_SZ);
    const uint32_t sbase = (uint32_t)__cvta_generic_to_shared(smbuf);

    // Stage 128 Q rows (raw bits) into stage 0, extract frags, then recycle.
    {
        const float4* gq = (const float4*)(g_q + bh + (size_t)q0 * DH_SZ);
        for (int idx = tid; idx < 2048; idx += 256) {
            const int r = idx >> 4, c = (idx & 15) << 2;
            cp16(sbase + (r * PK + c) * 4, gq + idx);
        }
        asm volatile("cp.async.commit_group;\n");
        asm volatile("cp.async.wait_group 0;\n");
        __syncthreads();
    }

    const float qsc = 0.125f * LOG2E;   // score scale folded with log2e
    uint32_t qf[8][4];
    {
        const int r = warp * 16 + g;
        const uint32_t* b0 = &smbuf[r * PK];
        const uint32_t* b1 = &smbuf[(r + 8) * PK];
#pragma unroll
        for (int k8 = 0; k8 < 8; k8++) {
            const int k = k8 * 8;
            qf[k8][0] = f2tf32(qsc * __uint_as_float(b0[k + tg]));
            qf[k8][1] = f2tf32(qsc * __uint_as_float(b1[k + tg]));
            qf[k8][2] = f2tf32(qsc * __uint_as_float(b0[k + tg + 4]));
            qf[k8][3] = f2tf32(qsc * __uint_as_float(b1[k + tg + 4]));
        }
    }
    __syncthreads();

    const float4* gkb = (const float4*)(g_k + bh);
    const float4* gvb = (const float4*)(g_v + bh);

    auto issue_tile = [&](int t, int stage) {
        const uint32_t kb = sbase + (stage * STAGE_W) * 4;
        const uint32_t vb = kb + (64 * PK) * 4;
        const float4* gk = gkb + (size_t)t * 1024;
        const float4* gv = gvb + (size_t)t * 1024;
#pragma unroll
        for (int u = 0; u < 4; u++) {
            const int idx = tid + 256 * u;
            const int r = idx >> 4, c = (idx & 15) << 2;
            cp16(kb + (r * PK + c) * 4, gk + idx);
            cp16(vb + (r * PK + c) * 4, gv + idx);
        }
        asm volatile("cp.async.commit_group;\n");
    };

    issue_tile(0, 0);
    issue_tile(1, 1);

    float of[8][4];
#pragma unroll
    for (int ni = 0; ni < 8; ni++)
#pragma unroll
        for (int c = 0; c < 4; c++) of[ni][c] = 0.f;
    float m0 = -1e30f, m1 = -1e30f, l0 = 0.f, l1 = 0.f;

    const int* mrow = mask + b * S_SZ;
    const int NT = S_SZ / 64;   // 32
    const float MNEG = -1e9f * LOG2E;   // mask constant in exp2 domain

    const int kq_col = (m4 >> 1) * 8 + (m4 & 1) * 4;

    int s = 0;
    for (int t = 0; t < NT; t++) {
        if (t + 1 < NT) asm volatile("cp.async.wait_group 1;\n");
        else            asm volatile("cp.async.wait_group 0;\n");
        __syncthreads();

        if (t + 2 < NT) {
            int s2 = s + 2; if (s2 >= 3) s2 -= 3;   // consumed last iter
            issue_tile(t + 2, s2);
        }

        const uint32_t kwb = sbase + (s * STAGE_W) * 4;
        const uint32_t* VsS = &smbuf[s * STAGE_W + 64 * PK];

        // S = (Q * qsc) K^T   (scores already in log2 units)
        float s_[8][4];
#pragma unroll
        for (int nt = 0; nt < 8; nt++) {
            s_[nt][0] = 0.f; s_[nt][1] = 0.f; s_[nt][2] = 0.f; s_[nt][3] = 0.f;
#pragma unroll
            for (int k8g = 0; k8g < 4; k8g++) {
                uint32_t d[4];
                ldsm_x4(d, kwb + ((nt * 8 + lm8) * PK + k8g * 16 + kq_col) * 4);
                mma16n8k8(s_[nt], qf[2 * k8g],     &d[0]);
                mma16n8k8(s_[nt], qf[2 * k8g + 1], &d[2]);
            }
        }

        // mask (additive, log2 domain), int2 loads
#pragma unroll
        for (int nt = 0; nt < 8; nt++) {
            const int2 mm = *(const int2*)&mrow[t * 64 + nt * 8 + tg * 2];
            const float ma = (mm.x == 0) ? MNEG : 0.f;
            const float mb = (mm.y == 0) ? MNEG : 0.f;
            s_[nt][0] += ma; s_[nt][1] += mb;
            s_[nt][2] += ma; s_[nt][3] += mb;
        }

        // online softmax in exp2 domain
        float rm0 = -1e30f, rm1 = -1e30f;
#pragma unroll
        for (int nt = 0; nt < 8; nt++) {
            rm0 = fmaxf(rm0, fmaxf(s_[nt][0], s_[nt][1]));
            rm1 = fmaxf(rm1, fmaxf(s_[nt][2], s_[nt][3]));
        }
        rm0 = fmaxf(rm0, __shfl_xor_sync(0xffffffffu, rm0, 1));
        rm0 = fmaxf(rm0, __shfl_xor_sync(0xffffffffu, rm0, 2));
        rm1 = fmaxf(rm1, __shfl_xor_sync(0xffffffffu, rm1, 1));
        rm1 = fmaxf(rm1, __shfl_xor_sync(0xffffffffu, rm1, 2));

        const float mn0 = fmaxf(m0, rm0);
        const float mn1 = fmaxf(m1, rm1);
        const float al0 = exp2f(m0 - mn0);   // == 1.0f exactly when max unchanged
        const float al1 = exp2f(m1 - mn1);
        m0 = mn0; m1 = mn1;

        float rs0 = 0.f, rs1 = 0.f;
#pragma unroll
        for (int nt = 0; nt < 8; nt++) {
            s_[nt][0] = exp2f(s_[nt][0] - mn0);
            s_[nt][1] = exp2f(s_[nt][1] - mn0);
            s_[nt][2] = exp2f(s_[nt][2] - mn1);
            s_[nt][3] = exp2f(s_[nt][3] - mn1);
            rs0 += s_[nt][0] + s_[nt][1];
            rs1 += s_[nt][2] + s_[nt][3];
        }
        rs0 += __shfl_xor_sync(0xffffffffu, rs0, 1);
        rs0 += __shfl_xor_sync(0xffffffffu, rs0, 2);
        rs1 += __shfl_xor_sync(0xffffffffu, rs1, 1);
        rs1 += __shfl_xor_sync(0xffffffffu, rs1, 2);
        l0 = l0 * al0 + rs0;
        l1 = l1 * al1 + rs1;

        // O-rescale only if some row's max increased (warp vote)
        if (!__all_sync(0xffffffffu, (al0 == 1.f) && (al1 == 1.f))) {
#pragma unroll
            for (int ni = 0; ni < 8; ni++) {
                of[ni][0] *= al0; of[ni][1] *= al0;
                of[ni][2] *= al1; of[ni][3] *= al1;
            }
        }

        // O += P V : permuted contraction, C-frag reused directly as A-frag
#pragma unroll
        for (int j = 0; j < 8; j++) {
            uint32_t pa[4];
            pa[0] = __float_as_uint(s_[j][0]);
            pa[1] = __float_as_uint(s_[j][2]);
            pa[2] = __float_as_uint(s_[j][1]);
            pa[3] = __float_as_uint(s_[j][3]);
            const uint32_t* vr0 = &VsS[(j * 8 + 2 * tg)     * PK];
            const uint32_t* vr1 = &VsS[(j * 8 + 2 * tg + 1) * PK];
#pragma unroll
            for (int ni = 0; ni < 8; ni++) {
                uint32_t bf[2];
                bf[0] = vr0[ni * 8 + g];
                bf[1] = vr1[ni * 8 + g];
                mma16n8k8(of[ni], pa, bf);
            }
        }

        if (++s == 3) s = 0;
    }

    const float il0 = 1.f / l0;
    const float il1 = 1.f / l1;
    const int row0 = b * S_SZ + q0 + warp * 16 + g;
    const int colb = h * DH_SZ;
#pragma unroll
    for (int ni = 0; ni < 8; ni++) {
        const int col = colb + ni * 8 + tg * 2;
        float2 v0, v1;
        v0.x = of[ni][0] * il0; v0.y = of[ni][1] * il0;
        v1.x = of[ni][2] * il1; v1.y = of[ni][3] * il1;
        *(float2*)&g_ctx[(size_t)row0 * D_SZ + col]       = v0;
        *(float2*)&g_ctx[(size_t)(row0 + 8) * D_SZ + col] = v1;
    }
}

// ---------------------------------------------------------------------------
// LayerNorm over last dim (1024). float4 vectorized, two-pass (exact).
// ---------------------------------------------------------------------------
__global__ void __launch_bounds__(256)
ln_kernel(const float* __restrict__ gamma, const float* __restrict__ beta,
          float* __restrict__ out)
{
    __shared__ float red[8];
    const int row = blockIdx.x;
    const int tid = threadIdx.x;
    const float4 v = ((const float4*)(g_q + (size_t)row * D_SZ))[tid];

    float s = v.x + v.y + v.z + v.w;
#pragma unroll
    for (int off = 16; off > 0; off >>= 1)
        s += __shfl_xor_sync(0xffffffffu, s, off);
    if ((tid & 31) == 0) red[tid >> 5] = s;
    __syncthreads();
    float tot = 0.f;
#pragma unroll
    for (int w = 0; w < 8; w++) tot += red[w];
    const float mu = tot * (1.f / 1024.f);

    const float d0 = v.x - mu, d1 = v.y - mu, d2 = v.z - mu, d3 = v.w - mu;
    float ss = d0 * d0 + d1 * d1 + d2 * d2 + d3 * d3;
#pragma unroll
    for (int off = 16; off > 0; off >>= 1)
        ss += __shfl_xor_sync(0xffffffffu, ss, off);
    __syncthreads();
    if ((tid & 31) == 0) red[tid >> 5] = ss;
    __syncthreads();
    float vtot = 0.f;
#pragma unroll
    for (int w = 0; w < 8; w++) vtot += red[w];
    const float inv = rsqrtf(vtot * (1.f / 1024.f) + 1e-5f);

    const float4 ga = ((const float4*)gamma)[tid];
    const float4 be = ((const float4*)beta)[tid];
    float4 o;
    o.x = ga.x * d0 * inv + be.x;
    o.y = ga.y * d1 * inv + be.y;
    o.z = ga.z * d2 * inv + be.z;
    o.w = ga.w * d3 * inv + be.w;
    ((float4*)(out + (size_t)row * D_SZ))[tid] = o;
}

// ---------------------------------------------------------------------------
extern "C" void kernel_launch(void* const* d_in, const int* in_sizes, int n_in,
                              void* d_out, int out_size)
{
    const float* Q     = (const float*)d_in[0];
    const float* K     = (const float*)d_in[1];
    const float* V     = (const float*)d_in[2];
    const int*   mask  = (const int*)  d_in[3];
    const float* Wq    = (const float*)d_in[4];
    const float* bq    = (const float*)d_in[5];
    const float* Wk    = (const float*)d_in[6];
    const float* bk    = (const float*)d_in[7];
    const float* Wv    = (const float*)d_in[8];
    const float* bv    = (const float*)d_in[9];
    const float* Wo    = (const float*)d_in[10];
    const float* bo    = (const float*)d_in[11];
    const float* gamma = (const float*)d_in[12];
    const float* beta  = (const float*)d_in[13];
    float* out = (float*)d_out;

    cudaFuncSetAttribute(flash_mma,
                         cudaFuncAttributeMaxDynamicSharedMemorySize,
                         FLASH_SMEM_B);
    cudaFuncSetAttribute(gemm_qkv,
                         cudaFuncAttributeMaxDynamicSharedMemorySize,
                         GEMM_SMEM_B);
    cudaFuncSetAttribute(gemm_o,
                         cudaFuncAttributeMaxDynamicSharedMemorySize,
                         GEMM_SMEM_B);
    (void)cudaGetLastError();

    const dim3 qkv_grid(D_SZ / 128, M_SZ / 128, 3);
    const dim3 o_grid(D_SZ / 128, M_SZ / 128);

    gemm_qkv<<<qkv_grid, 256, GEMM_SMEM_B>>>(Q, K, V, Wq, Wk, Wv, bq, bk, bv);

    flash_mma<<<dim3(S_SZ / 128, H_SZ, B_SZ), 256, FLASH_SMEM_B>>>(mask);

    gemm_o<<<o_grid, 256, GEMM_SMEM_B>>>(Wo, bo, Q);

    ln_kernel<<<M_SZ, 256>>>(gamma, beta, out);
}

// round 17
// speedup vs baseline: 1.2956x; 1.2339x over previous
#include <cuda_runtime.h>
#include <cuda_fp16.h>
#include <cstdint>
#include <cstddef>

// ---------------------------------------------------------------------------
// MultiHeadAttention fused block (round 16: fp16 m16n8k16 flash attention;
// QKV GEMM epilogue emits pre-scaled fp16 q/k/v; GEMMs round-13 config).
// ---------------------------------------------------------------------------

#define B_SZ   4
#define S_SZ   2048
#define D_SZ   1024
#define H_SZ   16
#define DH_SZ  64
#define M_SZ   (B_SZ * S_SZ)          // 8192

#define PHW 36                         // flash smem pitch (words) per 64-half row
#define PHB (PHW * 4)                  // 144 bytes
#define STG_B (128 * PHB)              // stage: 64 K rows + 64 V rows = 18432 B
#define FLASH_SMEM_B (3 * STG_B)       // 55296 B

#define GP 36                          // gemm smem pitch (words)
#define GSTAGE (128 * GP * 2)
#define GEMM_SMEM_B (3 * GSTAGE * 4)   // 110592 B

#define LOG2E 1.44269504088896340736f
#define QSC (0.125f * LOG2E)

__device__ __half g_q16[M_SZ * D_SZ];  // projected q, pre-scaled by QSC, fp16
__device__ __half g_k16[M_SZ * D_SZ];  // projected k, fp16 (head-major)
__device__ __half g_v16[M_SZ * D_SZ];  // projected v, fp16 (head-major)
__device__ float  g_q[M_SZ * D_SZ];    // pre-LN x (gemm_o output)
__device__ float  g_ctx[M_SZ * D_SZ];  // merged-head ctx (B*S, D)

__device__ __forceinline__ uint32_t h2pack(float lo, float hi) {
    uint32_t r;
    asm("cvt.rn.f16x2.f32 %0, %1, %2;" : "=r"(r) : "f"(hi), "f"(lo));
    return r;
}

__device__ __forceinline__ void mma16n8k8(float c[4], const uint32_t a[4],
                                          const uint32_t b[2]) {
    asm volatile(
        "mma.sync.aligned.m16n8k8.row.col.f32.tf32.tf32.f32 "
        "{%0,%1,%2,%3}, {%4,%5,%6,%7}, {%8,%9}, {%0,%1,%2,%3};\n"
        : "+f"(c[0]), "+f"(c[1]), "+f"(c[2]), "+f"(c[3])
        : "r"(a[0]), "r"(a[1]), "r"(a[2]), "r"(a[3]), "r"(b[0]), "r"(b[1]));
}

__device__ __forceinline__ void mma16n8k16h(float c[4], const uint32_t a[4],
                                            const uint32_t b[2]) {
    asm volatile(
        "mma.sync.aligned.m16n8k16.row.col.f32.f16.f16.f32 "
        "{%0,%1,%2,%3}, {%4,%5,%6,%7}, {%8,%9}, {%0,%1,%2,%3};\n"
        : "+f"(c[0]), "+f"(c[1]), "+f"(c[2]), "+f"(c[3])
        : "r"(a[0]), "r"(a[1]), "r"(a[2]), "r"(a[3]), "r"(b[0]), "r"(b[1]));
}

__device__ __forceinline__ void cp16(uint32_t smem_dst, const void* gmem_src) {
    asm volatile("cp.async.cg.shared.global [%0], [%1], 16;\n"
                 :: "r"(smem_dst), "l"(gmem_src));
}

__device__ __forceinline__ void ldsm_x4(uint32_t d[4], uint32_t addr) {
    asm volatile("ldmatrix.sync.aligned.m8n8.x4.shared.b16 {%0,%1,%2,%3}, [%4];"
                 : "=r"(d[0]), "=r"(d[1]), "=r"(d[2]), "=r"(d[3]) : "r"(addr));
}

__device__ __forceinline__ void ldsm_x4t(uint32_t d[4], uint32_t addr) {
    asm volatile("ldmatrix.sync.aligned.m8n8.x4.trans.shared.b16 {%0,%1,%2,%3}, [%4];"
                 : "=r"(d[0]), "=r"(d[1]), "=r"(d[2]), "=r"(d[3]) : "r"(addr));
}

// ---------------------------------------------------------------------------
// Pipelined tf32 GEMM mainloop (round 13, proven best).
// ---------------------------------------------------------------------------
__device__ __forceinline__ void gemm_mainloop(
    const float* __restrict__ A, const float* __restrict__ W,
    int m0, int n0, uint32_t sbase, float acc[4][4][4])
{
    const int tid  = threadIdx.x;
    const int lane = tid & 31;
    const int warp = tid >> 5;
    const int wm   = (warp & 1) * 64;
    const int wn   = (warp >> 1) * 32;
    const int lm8  = lane & 7;
    const int m4   = lane >> 3;
    const int lr   = tid >> 3;
    const int lc   = (tid & 7) << 2;

#pragma unroll
    for (int mi = 0; mi < 4; mi++)
#pragma unroll
        for (int ni = 0; ni < 4; ni++)
#pragma unroll
            for (int c = 0; c < 4; c++) acc[mi][ni][c] = 0.f;

    auto issue = [&](int k0, int stage) {
        const uint32_t ab = sbase + (stage * GSTAGE) * 4;
        const uint32_t bb = ab + (128 * GP) * 4;
#pragma unroll
        for (int u = 0; u < 4; u++) {
            const int row = lr + 32 * u;
            cp16(ab + (row * GP + lc) * 4, A + (size_t)(m0 + row) * D_SZ + k0 + lc);
            cp16(bb + (row * GP + lc) * 4, W + (size_t)(n0 + row) * D_SZ + k0 + lc);
        }
        asm volatile("cp.async.commit_group;\n");
    };

    issue(0, 0);
    issue(32, 1);

    const int a_row = (m4 & 1) * 8 + lm8;
    const int a_col = (m4 >> 1) * 4;
    const int b_row = (m4 >> 1) * 8 + lm8;
    const int b_col = (m4 & 1) * 4;

    const int NK = D_SZ / 32;
    int s = 0;
    for (int kt = 0; kt < NK; kt++) {
        if (kt + 1 < NK) asm volatile("cp.async.wait_group 1;\n");
        else             asm volatile("cp.async.wait_group 0;\n");
        __syncthreads();

        if (kt + 2 < NK) {
            int s2 = s + 2; if (s2 >= 3) s2 -= 3;
            issue((kt + 2) * 32, s2);
        }

        const uint32_t aw = sbase + (s * GSTAGE) * 4;
        const uint32_t bw = aw + (128 * GP) * 4;

#pragma unroll
        for (int kk = 0; kk < 32; kk += 8) {
            uint32_t af[4][4], bf[4][2];
#pragma unroll
            for (int mi = 0; mi < 4; mi++)
                ldsm_x4(af[mi],
                        aw + ((wm + mi * 16 + a_row) * GP + kk + a_col) * 4);
#pragma unroll
            for (int np = 0; np < 4; np += 2)
                ldsm_x4(&bf[np][0],
                        bw + ((wn + np * 8 + b_row) * GP + kk + b_col) * 4);
#pragma unroll
            for (int mi = 0; mi < 4; mi++)
#pragma unroll
                for (int ni = 0; ni < 4; ni++)
                    mma16n8k8(acc[mi][ni], af[mi], bf[ni]);
        }

        if (++s == 3) s = 0;
    }
}

// ---------------------------------------------------------------------------
// Fused Q/K/V projection GEMM. Writes fp16 head-major; mode 0 pre-scales
// by QSC (folded softmax scale + log2e).
// ---------------------------------------------------------------------------
__global__ void __launch_bounds__(256, 2)
gemm_qkv(const float* __restrict__ Qin, const float* __restrict__ Kin,
         const float* __restrict__ Vin,
         const float* __restrict__ Wq, const float* __restrict__ Wk,
         const float* __restrict__ Wv,
         const float* __restrict__ bq, const float* __restrict__ bk,
         const float* __restrict__ bv)
{
    extern __shared__ uint32_t smbuf[];
    const uint32_t sbase = (uint32_t)__cvta_generic_to_shared(smbuf);

    const int mode = blockIdx.z;
    const float* A    = (mode == 0) ? Qin : (mode == 1) ? Kin : Vin;
    const float* W    = (mode == 0) ? Wq  : (mode == 1) ? Wk  : Wv;
    const float* bias = (mode == 0) ? bq  : (mode == 1) ? bk  : bv;
    __half* out       = (mode == 0) ? g_q16 : (mode == 1) ? g_k16 : g_v16;
    const float sc    = (mode == 0) ? QSC : 1.f;

    const int m0 = blockIdx.y * 128;
    const int n0 = blockIdx.x * 128;

    float acc[4][4][4];
    gemm_mainloop(A, W, m0, n0, sbase, acc);

    const int lane = threadIdx.x & 31;
    const int warp = threadIdx.x >> 5;
    const int wm = (warp & 1) * 64, wn = (warp >> 1) * 32;
    const int g = lane >> 2, tg = lane & 3;

#pragma unroll
    for (int mi = 0; mi < 4; mi++)
#pragma unroll
        for (int ni = 0; ni < 4; ni++)
#pragma unroll
            for (int h = 0; h < 2; h++) {
                const int m = m0 + wm + mi * 16 + g + h * 8;
                const int n = n0 + wn + ni * 8 + tg * 2;
                const int bI = m >> 11, s = m & 2047;
                const int head = n >> 6, dd = n & 63;
                const float vx = (acc[mi][ni][h * 2 + 0] + bias[n])     * sc;
                const float vy = (acc[mi][ni][h * 2 + 1] + bias[n + 1]) * sc;
                const size_t dst = ((size_t)(bI * H_SZ + head) << 17)
                                 + ((size_t)s << 6) + dd;
                *(uint32_t*)&out[dst] = h2pack(vx, vy);
            }
}

// ---------------------------------------------------------------------------
// Output projection GEMM: x = g_ctx @ Wo^T + bo + resid -> g_q.
// ---------------------------------------------------------------------------
__global__ void __launch_bounds__(256, 2)
gemm_o(const float* __restrict__ Wo, const float* __restrict__ bo,
       const float* __restrict__ resid)
{
    extern __shared__ uint32_t smbuf[];
    const uint32_t sbase = (uint32_t)__cvta_generic_to_shared(smbuf);

    const int m0 = blockIdx.y * 128;
    const int n0 = blockIdx.x * 128;

    float acc[4][4][4];
    gemm_mainloop((const float*)g_ctx, Wo, m0, n0, sbase, acc);

    const int lane = threadIdx.x & 31;
    const int warp = threadIdx.x >> 5;
    const int wm = (warp & 1) * 64, wn = (warp >> 1) * 32;
    const int g = lane >> 2, tg = lane & 3;

#pragma unroll
    for (int mi = 0; mi < 4; mi++)
#pragma unroll
        for (int ni = 0; ni < 4; ni++)
#pragma unroll
            for (int h = 0; h < 2; h++) {
                const int m = m0 + wm + mi * 16 + g + h * 8;
                const int n = n0 + wn + ni * 8 + tg * 2;
                const size_t idx = (size_t)m * D_SZ + n;
                const float2 r2 = *(const float2*)&resid[idx];
                float2 val;
                val.x = acc[mi][ni][h * 2 + 0] + bo[n]     + r2.x;
                val.y = acc[mi][ni][h * 2 + 1] + bo[n + 1] + r2.y;
                *(float2*)&g_q[idx] = val;
            }
}

// ---------------------------------------------------------------------------
// Flash attention, fp16 m16n8k16. 256 threads, Q tile 128 rows, KV tile 64,
// 3-stage cp.async. K B-frags: ldmatrix; V B-frags: ldmatrix.trans; P packs
// straight from the S C-fragment into the k16 A-fragment (cvt.f16x2 only).
// Softmax in exp2 domain (Q pre-scaled by QSC at projection time).
// ---------------------------------------------------------------------------
__global__ void __launch_bounds__(256, 2)
flash_mma(const int* __restrict__ mask)
{
    extern __shared__ uint32_t smbuf[];

    const int b    = blockIdx.z;
    const int h    = blockIdx.y;
    const int q0   = blockIdx.x * 128;
    const int tid  = threadIdx.x;
    const int lane = tid & 31;
    const int warp = tid >> 5;
    const int g    = lane >> 2;
    const int tg   = lane & 3;
    const int lm8  = lane & 7;
    const int m4   = lane >> 3;

    const size_t bh = (size_t)(b * H_SZ + h) * (S_SZ * DH_SZ);
    const uint32_t sbase = (uint32_t)__cvta_generic_to_shared(smbuf);

    // ---- Stage 128 Q rows (fp16, pre-scaled) into stage 0, extract frags ----
    {
        const __half* gq = g_q16 + bh + (size_t)q0 * DH_SZ;
#pragma unroll
        for (int u = 0; u < 4; u++) {
            const int idx = tid + 256 * u;      // 0..1023
            const int r = idx >> 3, c = idx & 7;
            const uint32_t addr = (r < 64)
                ? sbase + r * PHB + c * 16
                : sbase + 64 * PHB + (r - 64) * PHB + c * 16;
            cp16(addr, gq + r * 64 + c * 8);
        }
        asm volatile("cp.async.commit_group;\n");
        asm volatile("cp.async.wait_group 0;\n");
        __syncthreads();
    }

    uint32_t qf[4][4];   // [k16-group][a-frag]
    {
        const int rq = warp * 16 + (m4 & 1) * 8 + lm8;
        const uint32_t qb = (rq < 64)
            ? sbase + rq * PHB
            : sbase + 64 * PHB + (rq - 64) * PHB;
#pragma unroll
        for (int kg = 0; kg < 4; kg++)
            ldsm_x4(qf[kg], qb + kg * 32 + (m4 >> 1) * 16);
    }
    __syncthreads();   // Q reads done; stage 0 may be refilled

    const __half* gkb = g_k16 + bh;
    const __half* gvb = g_v16 + bh;

    auto issue_tile = [&](int t, int stage) {
        const uint32_t kb = sbase + stage * STG_B;
        const uint32_t vb = kb + 64 * PHB;
        const __half* gk = gkb + (size_t)t * 64 * 64;
        const __half* gv = gvb + (size_t)t * 64 * 64;
#pragma unroll
        for (int u = 0; u < 2; u++) {
            const int idx = tid + 256 * u;      // 0..511
            const int r = idx >> 3, c = idx & 7;
            cp16(kb + r * PHB + c * 16, gk + r * 64 + c * 8);
            cp16(vb + r * PHB + c * 16, gv + r * 64 + c * 8);
        }
        asm volatile("cp.async.commit_group;\n");
    };

    issue_tile(0, 0);
    issue_tile(1, 1);

    float of[8][4];
#pragma unroll
    for (int ni = 0; ni < 8; ni++)
#pragma unroll
        for (int c = 0; c < 4; c++) of[ni][c] = 0.f;
    float m0 = -1e30f, m1 = -1e30f, l0 = 0.f, l1 = 0.f;

    const int* mrow = mask + b * S_SZ;
    const int NT = S_SZ / 64;
    const float MNEG = -1e9f * LOG2E;

    int s = 0;
    for (int t = 0; t < NT; t++) {
        if (t + 1 < NT) asm volatile("cp.async.wait_group 1;\n");
        else            asm volatile("cp.async.wait_group 0;\n");
        __syncthreads();

        if (t + 2 < NT) {
            int s2 = s + 2; if (s2 >= 3) s2 -= 3;
            issue_tile(t + 2, s2);
        }

        const uint32_t kwb = sbase + s * STG_B;
        const uint32_t vwb = kwb + 64 * PHB;

        // S = Qs K^T  (scores in log2 units; 8 nt x 2 ldsm.x4 x 2 mma)
        float s_[8][4];
#pragma unroll
        for (int nt = 0; nt < 8; nt++) {
            s_[nt][0] = 0.f; s_[nt][1] = 0.f; s_[nt][2] = 0.f; s_[nt][3] = 0.f;
            const uint32_t krow = kwb + (nt * 8 + lm8) * PHB + m4 * 16;
#pragma unroll
            for (int kg2 = 0; kg2 < 2; kg2++) {
                uint32_t d[4];
                ldsm_x4(d, krow + kg2 * 64);
                mma16n8k16h(s_[nt], qf[2 * kg2],     &d[0]);
                mma16n8k16h(s_[nt], qf[2 * kg2 + 1], &d[2]);
            }
        }

        // mask (additive, log2 domain)
#pragma unroll
        for (int nt = 0; nt < 8; nt++) {
            const int2 mm = *(const int2*)&mrow[t * 64 + nt * 8 + tg * 2];
            const float ma = (mm.x == 0) ? MNEG : 0.f;
            const float mb = (mm.y == 0) ? MNEG : 0.f;
            s_[nt][0] += ma; s_[nt][1] += mb;
            s_[nt][2] += ma; s_[nt][3] += mb;
        }

        // online softmax in exp2 domain
        float rm0 = -1e30f, rm1 = -1e30f;
#pragma unroll
        for (int nt = 0; nt < 8; nt++) {
            rm0 = fmaxf(rm0, fmaxf(s_[nt][0], s_[nt][1]));
            rm1 = fmaxf(rm1, fmaxf(s_[nt][2], s_[nt][3]));
        }
        rm0 = fmaxf(rm0, __shfl_xor_sync(0xffffffffu, rm0, 1));
        rm0 = fmaxf(rm0, __shfl_xor_sync(0xffffffffu, rm0, 2));
        rm1 = fmaxf(rm1, __shfl_xor_sync(0xffffffffu, rm1, 1));
        rm1 = fmaxf(rm1, __shfl_xor_sync(0xffffffffu, rm1, 2));

        const float mn0 = fmaxf(m0, rm0);
        const float mn1 = fmaxf(m1, rm1);
        const float al0 = exp2f(m0 - mn0);
        const float al1 = exp2f(m1 - mn1);
        m0 = mn0; m1 = mn1;

        float rs0 = 0.f, rs1 = 0.f;
#pragma unroll
        for (int nt = 0; nt < 8; nt++) {
            s_[nt][0] = exp2f(s_[nt][0] - mn0);
            s_[nt][1] = exp2f(s_[nt][1] - mn0);
            s_[nt][2] = exp2f(s_[nt][2] - mn1);
            s_[nt][3] = exp2f(s_[nt][3] - mn1);
            rs0 += s_[nt][0] + s_[nt][1];
            rs1 += s_[nt][2] + s_[nt][3];
        }
        rs0 += __shfl_xor_sync(0xffffffffu, rs0, 1);
        rs0 += __shfl_xor_sync(0xffffffffu, rs0, 2);
        rs1 += __shfl_xor_sync(0xffffffffu, rs1, 1);
        rs1 += __shfl_xor_sync(0xffffffffu, rs1, 2);
        l0 = l0 * al0 + rs0;
        l1 = l1 * al1 + rs1;

        if (!__all_sync(0xffffffffu, (al0 == 1.f) && (al1 == 1.f))) {
#pragma unroll
            for (int ni = 0; ni < 8; ni++) {
                of[ni][0] *= al0; of[ni][1] *= al0;
                of[ni][2] *= al1; of[ni][3] *= al1;
            }
        }

        // O += P V : P C-frag packs directly into the k16 A-frag.
#pragma unroll
        for (int j2 = 0; j2 < 4; j2++) {
            uint32_t pa[4];
            pa[0] = h2pack(s_[2 * j2][0],     s_[2 * j2][1]);
            pa[1] = h2pack(s_[2 * j2][2],     s_[2 * j2][3]);
            pa[2] = h2pack(s_[2 * j2 + 1][0], s_[2 * j2 + 1][1]);
            pa[3] = h2pack(s_[2 * j2 + 1][2], s_[2 * j2 + 1][3]);
            const uint32_t vrow = vwb + (j2 * 16 + (m4 & 1) * 8 + lm8) * PHB
                                + (m4 >> 1) * 16;
#pragma unroll
            for (int ni2 = 0; ni2 < 4; ni2++) {
                uint32_t d[4];
                ldsm_x4t(d, vrow + ni2 * 32);
                mma16n8k16h(of[2 * ni2],     pa, &d[0]);
                mma16n8k16h(of[2 * ni2 + 1], pa, &d[2]);
            }
        }

        if (++s == 3) s = 0;
    }

    const float il0 = 1.f / l0;
    const float il1 = 1.f / l1;
    const int row0 = b * S_SZ + q0 + warp * 16 + g;
    const int colb = h * DH_SZ;
#pragma unroll
    for (int ni = 0; ni < 8; ni++) {
        const int col = colb + ni * 8 + tg * 2;
        float2 v0, v1;
        v0.x = of[ni][0] * il0; v0.y = of[ni][1] * il0;
        v1.x = of[ni][2] * il1; v1.y = of[ni][3] * il1;
        *(float2*)&g_ctx[(size_t)row0 * D_SZ + col]       = v0;
        *(float2*)&g_ctx[(size_t)(row0 + 8) * D_SZ + col] = v1;
    }
}

// ---------------------------------------------------------------------------
// LayerNorm over last dim (1024). float4 vectorized, two-pass (exact).
// ---------------------------------------------------------------------------
__global__ void __launch_bounds__(256)
ln_kernel(const float* __restrict__ gamma, const float* __restrict__ beta,
          float* __restrict__ out)
{
    __shared__ float red[8];
    const int row = blockIdx.x;
    const int tid = threadIdx.x;
    const float4 v = ((const float4*)(g_q + (size_t)row * D_SZ))[tid];

    float s = v.x + v.y + v.z + v.w;
#pragma unroll
    for (int off = 16; off > 0; off >>= 1)
        s += __shfl_xor_sync(0xffffffffu, s, off);
    if ((tid & 31) == 0) red[tid >> 5] = s;
    __syncthreads();
    float tot = 0.f;
#pragma unroll
    for (int w = 0; w < 8; w++) tot += red[w];
    const float mu = tot * (1.f / 1024.f);

    const float d0 = v.x - mu, d1 = v.y - mu, d2 = v.z - mu, d3 = v.w - mu;
    float ss = d0 * d0 + d1 * d1 + d2 * d2 + d3 * d3;
#pragma unroll
    for (int off = 16; off > 0; off >>= 1)
        ss += __shfl_xor_sync(0xffffffffu, ss, off);
    __syncthreads();
    if ((tid & 31) == 0) red[tid >> 5] = ss;
    __syncthreads();
    float vtot = 0.f;
#pragma unroll
    for (int w = 0; w < 8; w++) vtot += red[w];
    const float inv = rsqrtf(vtot * (1.f / 1024.f) + 1e-5f);

    const float4 ga = ((const float4*)gamma)[tid];
    const float4 be = ((const float4*)beta)[tid];
    float4 o;
    o.x = ga.x * d0 * inv + be.x;
    o.y = ga.y * d1 * inv + be.y;
    o.z = ga.z * d2 * inv + be.z;
    o.w = ga.w * d3 * inv + be.w;
    ((float4*)(out + (size_t)row * D_SZ))[tid] = o;
}

// ---------------------------------------------------------------------------
extern "C" void kernel_launch(void* const* d_in, const int* in_sizes, int n_in,
                              void* d_out, int out_size)
{
    const float* Q     = (const float*)d_in[0];
    const float* K     = (const float*)d_in[1];
    const float* V     = (const float*)d_in[2];
    const int*   mask  = (const int*)  d_in[3];
    const float* Wq    = (const float*)d_in[4];
    const float* bq    = (const float*)d_in[5];
    const float* Wk    = (const float*)d_in[6];
    const float* bk    = (const float*)d_in[7];
    const float* Wv    = (const float*)d_in[8];
    const float* bv    = (const float*)d_in[9];
    const float* Wo    = (const float*)d_in[10];
    const float* bo    = (const float*)d_in[11];
    const float* gamma = (const float*)d_in[12];
    const float* beta  = (const float*)d_in[13];
    float* out = (float*)d_out;

    cudaFuncSetAttribute(flash_mma,
                         cudaFuncAttributeMaxDynamicSharedMemorySize,
                         FLASH_SMEM_B);
    cudaFuncSetAttribute(gemm_qkv,
                         cudaFuncAttributeMaxDynamicSharedMemorySize,
                         GEMM_SMEM_B);
    cudaFuncSetAttribute(gemm_o,
                         cudaFuncAttributeMaxDynamicSharedMemorySize,
                         GEMM_SMEM_B);
    (void)cudaGetLastError();

    const dim3 qkv_grid(D_SZ / 128, M_SZ / 128, 3);
    const dim3 o_grid(D_SZ / 128, M_SZ / 128);

    gemm_qkv<<<qkv_grid, 256, GEMM_SMEM_B>>>(Q, K, V, Wq, Wk, Wv, bq, bk, bv);

    flash_mma<<<dim3(S_SZ / 128, H_SZ, B_SZ), 256, FLASH_SMEM_B>>>(mask);

    gemm_o<<<o_grid, 256, GEMM_SMEM_B>>>(Wo, bo, Q);

    ln_kernel<<<M_SZ, 256>>>(gamma, beta, out);
}